// round 11
// baseline (speedup 1.0000x reference)
#include <cuda_runtime.h>

#define NPTS   8192
#define NB     2
#define KNN    10
#define K2     11               /* KNN + self slot                    */
#define QPB    128              /* queries per CTA                    */
#define SPLIT  4                /* threads per query                  */
#define BLOCK  (QPB * SPLIT)    /* 512                                */
#define LSUB   (NPTS / SPLIT)   /* 2048 candidates per thread         */
#define BPB    (NPTS / QPB)     /* 64 blocks per batch                */
#define NBLOCKS (NB * BPB)      /* 128 total blocks                   */
#define VEC    8

#define SMEM_SP_BYTES   (NPTS * 16)                       /* 131072 */
#define SMEM_LIST_U32   (QPB * (SPLIT - 1) * K2)          /* 4224   */
#define SMEM_THR_BYTES  (QPB * 4)                         /* 512    */
#define SMEM_TOTAL      (SMEM_SP_BYTES + SMEM_LIST_U32 * 4 + SMEM_THR_BYTES)

__device__ float g_partial[NBLOCKS];

__device__ __forceinline__ void net_insert(unsigned nd[K2], unsigned ck)
{
    bool tk[K2];
#pragma unroll
    for (int t = 0; t < K2; ++t) tk[t] = ck < nd[t];
#pragma unroll
    for (int t = K2 - 1; t >= 1; --t)
        nd[t] = tk[t] ? (tk[t-1] ? nd[t-1] : ck) : nd[t];
    nd[0] = tk[0] ? ck : nd[0];
}

__global__ void __launch_bounds__(BLOCK, 1) knn_lap_kernel(
    const float* __restrict__ p1, const float* __restrict__ p2)
{
    extern __shared__ char smem_raw[];
    float4*   sp      = (float4*)smem_raw;                 // 8192 * 16B = 128 KB
    unsigned* slist   = (unsigned*)(smem_raw + SMEM_SP_BYTES);
    unsigned* sthresh = (unsigned*)(smem_raw + SMEM_SP_BYTES + SMEM_LIST_U32 * 4);

    const int b = blockIdx.y;
    const float* base1 = p1 + (size_t)b * NPTS * 3;
    const float* base2 = p2 + (size_t)b * NPTS * 3;

    // Stage full batch-b point1 cloud into shared memory as (x,y,z,|p|^2).
    for (int j = threadIdx.x; j < NPTS; j += BLOCK) {
        float x = base1[3*j+0];
        float y = base1[3*j+1];
        float z = base1[3*j+2];
        sp[j] = make_float4(x, y, z, fmaf(x, x, fmaf(y, y, z*z)));
    }
    if (threadIdx.x < QPB) sthresh[threadIdx.x] = 0xFFFFFFFFu;
    __syncthreads();

    const int tq  = threadIdx.x & (QPB - 1);   // query slot within CTA
    const int sub = threadIdx.x >> 7;          // substream 0..3
    const int qi  = blockIdx.x * QPB + tq;     // global query index
    const float4 q = sp[qi];
    const float n2x = -2.0f * q.x, n2y = -2.0f * q.y, n2z = -2.0f * q.z;
    const float qw  = q.w;
    unsigned* cell = &sthresh[tq];

    // K2-smallest keys over this substream. key = bits(full d^2) with low 13
    // mantissa bits replaced by candidate index (keys unique, order ~ distance).
    // Self has d^2 == 0 exactly -> key == qi -> always global min.
    unsigned nd[K2];
#pragma unroll
    for (int t = 0; t < K2; ++t) nd[t] = 0xFFFFFFFFu;
    unsigned thresh = 0xFFFFFFFFu;

    const int jbeg = sub * LSUB;
    const int jend = jbeg + LSUB;
    for (int j0 = jbeg; j0 < jend; j0 += VEC) {
        // Shared threshold: min over substreams' published 11th-best keys.
        // Any published value >= global 11th-best key, so pruning is exact.
        unsigned sharedT = *cell;                 // LDS.32, conflict-free
        unsigned eff = min(thresh, sharedT);

        unsigned key[VEC];
#pragma unroll
        for (int u = 0; u < VEC; ++u) {
            float4 c = sp[j0 + u];
            float d2 = fmaf(n2x, c.x, fmaf(n2y, c.y, fmaf(n2z, c.z, c.w + qw)));
            d2 = fmaxf(d2, 0.0f);
            key[u] = (__float_as_uint(d2) & 0xFFFFE000u) | (unsigned)(j0 + u);
        }
        unsigned m0 = min(key[0], key[1]);
        unsigned m1 = min(key[2], key[3]);
        unsigned m2 = min(key[4], key[5]);
        unsigned m3 = min(key[6], key[7]);
        unsigned mn = min(min(m0, m1), min(m2, m3));

        while (mn < eff) {               // rare once shared threshold tightens
            net_insert(nd, mn);
            thresh = nd[K2-1];
            eff = min(thresh, sharedT);
#pragma unroll
            for (int u = 0; u < VEC; ++u)        // mask inserted key (unique)
                key[u] = (key[u] == mn) ? 0xFFFFFFFFu : key[u];
            m0 = min(key[0], key[1]);
            m1 = min(key[2], key[3]);
            m2 = min(key[4], key[5]);
            m3 = min(key[6], key[7]);
            mn = min(min(m0, m1), min(m2, m3));
        }
        // Publish improved threshold (racy last-writer-wins; always safe).
        if (thresh < sharedT) *cell = thresh;     // predicated STS
    }

    // Substreams 1..3 publish lists; substream 0 merges 3*K2 foreign keys.
    if (sub) {
#pragma unroll
        for (int t = 0; t < K2; ++t)
            slist[((sub - 1) * QPB + tq) * K2 + t] = nd[t];
    }
    __syncthreads();

    float acc = 0.0f;
    if (sub == 0) {
        for (int s = 0; s < SPLIT - 1; ++s)
#pragma unroll
            for (int t = 0; t < K2; ++t) {
                unsigned ck = slist[(s * QPB + tq) * K2 + t];
                if (ck < nd[K2-1]) net_insert(nd, ck);
            }

        // nd[0..10] = 11 nearest incl. self. Skip self by index at readout.
        float s1x = 0.f, s1y = 0.f, s1z = 0.f;
        float s2x = 0.f, s2y = 0.f, s2z = 0.f;
#pragma unroll
        for (int t = 0; t < K2; ++t) {
            int idx = (int)(nd[t] & 0x1FFFu);
            if (idx != qi) {
                float4 c = sp[idx];
                s1x += c.x; s1y += c.y; s1z += c.z;
                const float* pp = base2 + 3 * idx;
                s2x += __ldg(pp + 0);
                s2y += __ldg(pp + 1);
                s2z += __ldg(pp + 2);
            }
        }
        float q2x = __ldg(base2 + 3*qi + 0);
        float q2y = __ldg(base2 + 3*qi + 1);
        float q2z = __ldg(base2 + 3*qi + 2);

        const float inv = 1.0f / (float)KNN;
        acc = fabsf((s1x*inv - q.x) - (s2x*inv - q2x))
            + fabsf((s1y*inv - q.y) - (s2y*inv - q2y))
            + fabsf((s1z*inv - q.z) - (s2z*inv - q2z));
    }

    // Deterministic block reduction over 16 warps (non-owner lanes carry 0).
    __syncthreads();
    __shared__ float sred[BLOCK / 32];
#pragma unroll
    for (int o = 16; o > 0; o >>= 1)
        acc += __shfl_down_sync(0xffffffffu, acc, o);
    if ((threadIdx.x & 31) == 0) sred[threadIdx.x >> 5] = acc;
    __syncthreads();
    if (threadIdx.x == 0) {
        float s = 0.f;
#pragma unroll
        for (int w = 0; w < BLOCK / 32; ++w) s += sred[w];
        g_partial[blockIdx.y * BPB + blockIdx.x] = s;
    }
}

__global__ void finalize_kernel(float* __restrict__ out)
{
    __shared__ float s[NBLOCKS];
    int t = threadIdx.x;
    s[t] = g_partial[t];
    __syncthreads();
#pragma unroll
    for (int o = NBLOCKS / 2; o > 0; o >>= 1) {
        if (t < o) s[t] += s[t + o];
        __syncthreads();
    }
    if (t == 0) out[0] = s[0] * (1.0f / (float)(NB * NPTS * 3));
}

extern "C" void kernel_launch(void* const* d_in, const int* in_sizes, int n_in,
                              void* d_out, int out_size)
{
    (void)in_sizes; (void)n_in; (void)out_size;
    const float* p1 = (const float*)d_in[0];
    const float* p2 = (const float*)d_in[1];

    cudaFuncSetAttribute(knn_lap_kernel,
                         cudaFuncAttributeMaxDynamicSharedMemorySize,
                         SMEM_TOTAL);

    dim3 grid(BPB, NB);
    knn_lap_kernel<<<grid, BLOCK, SMEM_TOTAL>>>(p1, p2);
    finalize_kernel<<<1, NBLOCKS>>>((float*)d_out);
}

// round 12
// speedup vs baseline: 1.6240x; 1.6240x over previous
#include <cuda_runtime.h>

#define NPTS   8192
#define NB     2
#define KNN    10
#define K2     11               /* KNN + self slot                    */
#define QPB    128              /* queries per CTA                    */
#define SPLIT  4                /* threads per query                  */
#define BLOCK  (QPB * SPLIT)    /* 512                                */
#define LSUB   (NPTS / SPLIT)   /* 2048 candidates per thread         */
#define BPB    (NPTS / QPB)     /* 64 blocks per batch                */
#define NBLOCKS (NB * BPB)      /* 128 total blocks                   */
#define VEC    16
#define NCHUNK 8                /* checkpoints between chunks         */
#define BLKS_PER_CHUNK (LSUB / VEC / NCHUNK)   /* 16 */

#define SMEM_SP_BYTES   (NPTS * 16)                       /* 131072 */
#define SMEM_LIST_U32   (QPB * (SPLIT - 1) * K2)          /* 4224   */
#define SMEM_THR_U32    (2 * QPB * SPLIT)                 /* double-buffered */
#define SMEM_TOTAL      (SMEM_SP_BYTES + (SMEM_LIST_U32 + SMEM_THR_U32) * 4)

__device__ float g_partial[NBLOCKS];

__device__ __forceinline__ void net_insert(unsigned nd[K2], unsigned ck)
{
    bool tk[K2];
#pragma unroll
    for (int t = 0; t < K2; ++t) tk[t] = ck < nd[t];
#pragma unroll
    for (int t = K2 - 1; t >= 1; --t)
        nd[t] = tk[t] ? (tk[t-1] ? nd[t-1] : ck) : nd[t];
    nd[0] = tk[0] ? ck : nd[0];
}

__device__ __forceinline__ unsigned min16(const unsigned k[VEC])
{
    unsigned a0 = min(k[0], k[1]),  a1 = min(k[2], k[3]);
    unsigned a2 = min(k[4], k[5]),  a3 = min(k[6], k[7]);
    unsigned a4 = min(k[8], k[9]),  a5 = min(k[10], k[11]);
    unsigned a6 = min(k[12], k[13]), a7 = min(k[14], k[15]);
    unsigned b0 = min(a0, a1), b1 = min(a2, a3);
    unsigned b2 = min(a4, a5), b3 = min(a6, a7);
    return min(min(b0, b1), min(b2, b3));
}

__global__ void __launch_bounds__(BLOCK, 1) knn_lap_kernel(
    const float* __restrict__ p1, const float* __restrict__ p2)
{
    extern __shared__ char smem_raw[];
    float4*   sp    = (float4*)smem_raw;                   // 8192 * 16B = 128 KB
    unsigned* slist = (unsigned*)(smem_raw + SMEM_SP_BYTES);
    unsigned* sthr  = slist + SMEM_LIST_U32;               // [2][QPB][SPLIT]

    const int b = blockIdx.y;
    const float* base1 = p1 + (size_t)b * NPTS * 3;
    const float* base2 = p2 + (size_t)b * NPTS * 3;

    // Stage full batch-b point1 cloud into shared memory as (x,y,z,|p|^2).
    for (int j = threadIdx.x; j < NPTS; j += BLOCK) {
        float x = base1[3*j+0];
        float y = base1[3*j+1];
        float z = base1[3*j+2];
        sp[j] = make_float4(x, y, z, fmaf(x, x, fmaf(y, y, z*z)));
    }
    __syncthreads();

    const int tq  = threadIdx.x & (QPB - 1);   // query slot within CTA
    const int sub = threadIdx.x >> 7;          // substream 0..3
    const int qi  = blockIdx.x * QPB + tq;     // global query index
    const float4 q = sp[qi];
    const float n2x = -2.0f * q.x, n2y = -2.0f * q.y, n2z = -2.0f * q.z;
    const float qw  = q.w;

    // K2-smallest keys over this substream. key = bits(full d^2) with low 13
    // mantissa bits replaced by candidate index (keys unique, order ~ distance).
    // Self has d^2 == 0 exactly -> key == qi -> always global min.
    unsigned nd[K2];
#pragma unroll
    for (int t = 0; t < K2; ++t) nd[t] = 0xFFFFFFFFu;
    unsigned thresh = 0xFFFFFFFFu;   // own 11th-best
    unsigned eff    = 0xFFFFFFFFu;   // min(own, shared) — prune threshold

    const int jbeg = sub * LSUB;
    int j0 = jbeg;
    for (int chunk = 0; chunk < NCHUNK; ++chunk) {
        if (chunk) {
            // Checkpoint: share 11th-best across the 4 substreams of this query.
            // Double-buffered by chunk parity -> single barrier suffices.
            const int par = chunk & 1;
            sthr[(par * QPB + tq) * SPLIT + sub] = thresh;
            __syncthreads();
            const unsigned* v = &sthr[(par * QPB + tq) * SPLIT];
            unsigned sharedT = min(min(v[0], v[1]), min(v[2], v[3]));
            eff = min(eff, sharedT);
        }

        for (int blk = 0; blk < BLKS_PER_CHUNK; ++blk, j0 += VEC) {
            unsigned key[VEC];
#pragma unroll
            for (int u = 0; u < VEC; ++u) {
                float4 c = sp[j0 + u];
                float d2 = fmaf(n2x, c.x, fmaf(n2y, c.y, fmaf(n2z, c.z, c.w + qw)));
                d2 = fmaxf(d2, 0.0f);
                key[u] = (__float_as_uint(d2) & 0xFFFFE000u) | (unsigned)(j0 + u);
            }
            unsigned mn = min16(key);

            while (mn < eff) {           // rare once shared threshold tightens
                net_insert(nd, mn);
                thresh = nd[K2-1];
                eff = min(eff, thresh);
#pragma unroll
                for (int u = 0; u < VEC; ++u)    // mask inserted key (unique)
                    key[u] = (key[u] == mn) ? 0xFFFFFFFFu : key[u];
                mn = min16(key);
            }
        }
    }

    // Substreams 1..3 publish lists; substream 0 merges 3*K2 foreign keys.
    if (sub) {
#pragma unroll
        for (int t = 0; t < K2; ++t)
            slist[((sub - 1) * QPB + tq) * K2 + t] = nd[t];
    }
    __syncthreads();

    float acc = 0.0f;
    if (sub == 0) {
        for (int s = 0; s < SPLIT - 1; ++s)
#pragma unroll
            for (int t = 0; t < K2; ++t) {
                unsigned ck = slist[(s * QPB + tq) * K2 + t];
                if (ck < nd[K2-1]) net_insert(nd, ck);
            }

        // nd[0..10] = 11 nearest incl. self. Skip self by index at readout.
        float s1x = 0.f, s1y = 0.f, s1z = 0.f;
        float s2x = 0.f, s2y = 0.f, s2z = 0.f;
#pragma unroll
        for (int t = 0; t < K2; ++t) {
            int idx = (int)(nd[t] & 0x1FFFu);
            if (idx != qi) {
                float4 c = sp[idx];
                s1x += c.x; s1y += c.y; s1z += c.z;
                const float* pp = base2 + 3 * idx;
                s2x += __ldg(pp + 0);
                s2y += __ldg(pp + 1);
                s2z += __ldg(pp + 2);
            }
        }
        float q2x = __ldg(base2 + 3*qi + 0);
        float q2y = __ldg(base2 + 3*qi + 1);
        float q2z = __ldg(base2 + 3*qi + 2);

        const float inv = 1.0f / (float)KNN;
        acc = fabsf((s1x*inv - q.x) - (s2x*inv - q2x))
            + fabsf((s1y*inv - q.y) - (s2y*inv - q2y))
            + fabsf((s1z*inv - q.z) - (s2z*inv - q2z));
    }

    // Deterministic block reduction over 16 warps (non-owner lanes carry 0).
    __syncthreads();
    __shared__ float sred[BLOCK / 32];
#pragma unroll
    for (int o = 16; o > 0; o >>= 1)
        acc += __shfl_down_sync(0xffffffffu, acc, o);
    if ((threadIdx.x & 31) == 0) sred[threadIdx.x >> 5] = acc;
    __syncthreads();
    if (threadIdx.x == 0) {
        float s = 0.f;
#pragma unroll
        for (int w = 0; w < BLOCK / 32; ++w) s += sred[w];
        g_partial[blockIdx.y * BPB + blockIdx.x] = s;
    }
}

__global__ void finalize_kernel(float* __restrict__ out)
{
    __shared__ float s[NBLOCKS];
    int t = threadIdx.x;
    s[t] = g_partial[t];
    __syncthreads();
#pragma unroll
    for (int o = NBLOCKS / 2; o > 0; o >>= 1) {
        if (t < o) s[t] += s[t + o];
        __syncthreads();
    }
    if (t == 0) out[0] = s[0] * (1.0f / (float)(NB * NPTS * 3));
}

extern "C" void kernel_launch(void* const* d_in, const int* in_sizes, int n_in,
                              void* d_out, int out_size)
{
    (void)in_sizes; (void)n_in; (void)out_size;
    const float* p1 = (const float*)d_in[0];
    const float* p2 = (const float*)d_in[1];

    cudaFuncSetAttribute(knn_lap_kernel,
                         cudaFuncAttributeMaxDynamicSharedMemorySize,
                         SMEM_TOTAL);

    dim3 grid(BPB, NB);
    knn_lap_kernel<<<grid, BLOCK, SMEM_TOTAL>>>(p1, p2);
    finalize_kernel<<<1, NBLOCKS>>>((float*)d_out);
}

// round 13
// speedup vs baseline: 1.7126x; 1.0546x over previous
#include <cuda_runtime.h>

#define NPTS   8192
#define NB     2
#define KNN    10
#define K2     11               /* KNN + self slot                    */
#define QPB    128              /* queries per CTA                    */
#define SPLIT  4                /* threads per query                  */
#define BLOCK  (QPB * SPLIT)    /* 512                                */
#define LSUB   (NPTS / SPLIT)   /* 2048 candidates per thread         */
#define BPB    (NPTS / QPB)     /* 64 blocks per batch                */
#define NBLOCKS (NB * BPB)      /* 128 total blocks                   */
#define VEC    16
#define NCHUNK 7                /* front-loaded checkpoint schedule   */

#define SMEM_SP_BYTES   (NPTS * 16)                       /* 131072 */
#define SMEM_LIST_U32   (QPB * (SPLIT - 1) * K2)          /* 4224   */
#define SMEM_THR_U32    (2 * QPB * SPLIT)                 /* double-buffered */
#define SMEM_TOTAL      (SMEM_SP_BYTES + (SMEM_LIST_U32 + SMEM_THR_U32) * 4)

__device__ float g_partial[NBLOCKS];

__device__ __forceinline__ void net_insert(unsigned nd[K2], unsigned ck)
{
    bool tk[K2];
#pragma unroll
    for (int t = 0; t < K2; ++t) tk[t] = ck < nd[t];
#pragma unroll
    for (int t = K2 - 1; t >= 1; --t)
        nd[t] = tk[t] ? (tk[t-1] ? nd[t-1] : ck) : nd[t];
    nd[0] = tk[0] ? ck : nd[0];
}

__device__ __forceinline__ unsigned min16(const unsigned k[VEC])
{
    unsigned a0 = min(k[0], k[1]),  a1 = min(k[2], k[3]);
    unsigned a2 = min(k[4], k[5]),  a3 = min(k[6], k[7]);
    unsigned a4 = min(k[8], k[9]),  a5 = min(k[10], k[11]);
    unsigned a6 = min(k[12], k[13]), a7 = min(k[14], k[15]);
    unsigned b0 = min(a0, a1), b1 = min(a2, a3);
    unsigned b2 = min(a4, a5), b3 = min(a6, a7);
    return min(min(b0, b1), min(b2, b3));
}

__global__ void __launch_bounds__(BLOCK, 1) knn_lap_kernel(
    const float* __restrict__ p1, const float* __restrict__ p2)
{
    extern __shared__ char smem_raw[];
    float4*   sp    = (float4*)smem_raw;                   // 8192 * 16B = 128 KB
    unsigned* slist = (unsigned*)(smem_raw + SMEM_SP_BYTES);
    unsigned* sthr  = slist + SMEM_LIST_U32;               // [2][QPB][SPLIT]

    const int b = blockIdx.y;
    const float* base1 = p1 + (size_t)b * NPTS * 3;
    const float* base2 = p2 + (size_t)b * NPTS * 3;

    // Stage full batch-b point1 cloud into shared memory as (x,y,z,|p|^2).
    for (int j = threadIdx.x; j < NPTS; j += BLOCK) {
        float x = base1[3*j+0];
        float y = base1[3*j+1];
        float z = base1[3*j+2];
        sp[j] = make_float4(x, y, z, fmaf(x, x, fmaf(y, y, z*z)));
    }
    __syncthreads();

    const int tq  = threadIdx.x & (QPB - 1);   // query slot within CTA
    const int sub = threadIdx.x >> 7;          // substream 0..3
    const int qi  = blockIdx.x * QPB + tq;     // global query index
    const float4 q = sp[qi];
    const float n2x = -2.0f * q.x, n2y = -2.0f * q.y, n2z = -2.0f * q.z;
    const float qw  = q.w;

    // K2-smallest keys over this substream. key = bits(full d^2) with low 13
    // mantissa bits replaced by candidate index (keys unique, order ~ distance).
    // Self has d^2 == 0 exactly -> key == qi -> always global min.
    unsigned nd[K2];
#pragma unroll
    for (int t = 0; t < K2; ++t) nd[t] = 0xFFFFFFFFu;
    unsigned thresh = 0xFFFFFFFFu;   // own 11th-best
    unsigned eff    = 0xFFFFFFFFu;   // min(own, shared) — prune threshold

    // Front-loaded schedule: first checkpoint after just 64 cand/thread
    // (256 pooled per query) so eff is tight before the bulk of the scan.
    const int jbeg = sub * LSUB;
    int j0 = jbeg;
#pragma unroll
    for (int chunk = 0; chunk < NCHUNK; ++chunk) {
        const int nblk = (chunk == 0) ? 4 : (chunk == 1) ? 8 :
                         (chunk == 2) ? 16 : (chunk == 3 || chunk == 4) ? 24 : 26;
        if (chunk) {
            // Share 11th-best across the 4 substreams of this query.
            // Double-buffered by chunk parity -> single barrier suffices.
            const int par = chunk & 1;
            sthr[(par * QPB + tq) * SPLIT + sub] = thresh;
            __syncthreads();
            const unsigned* v = &sthr[(par * QPB + tq) * SPLIT];
            unsigned sharedT = min(min(v[0], v[1]), min(v[2], v[3]));
            eff = min(eff, sharedT);
        }

        for (int blk = 0; blk < nblk; ++blk, j0 += VEC) {
            unsigned key[VEC];
#pragma unroll
            for (int u = 0; u < VEC; ++u) {
                float4 c = sp[j0 + u];
                float d2 = fmaf(n2x, c.x, fmaf(n2y, c.y, fmaf(n2z, c.z, c.w + qw)));
                d2 = fmaxf(d2, 0.0f);
                key[u] = (__float_as_uint(d2) & 0xFFFFE000u) | (unsigned)(j0 + u);
            }
            unsigned mn = min16(key);

            while (mn < eff) {           // rare once shared threshold tightens
                net_insert(nd, mn);
                thresh = nd[K2-1];
                eff = min(eff, thresh);
#pragma unroll
                for (int u = 0; u < VEC; ++u)    // mask inserted key (unique)
                    key[u] = (key[u] == mn) ? 0xFFFFFFFFu : key[u];
                mn = min16(key);
            }
        }
    }

    // Substreams 1..3 publish lists; substream 0 merges 3*K2 foreign keys.
    if (sub) {
#pragma unroll
        for (int t = 0; t < K2; ++t)
            slist[((sub - 1) * QPB + tq) * K2 + t] = nd[t];
    }
    __syncthreads();

    float acc = 0.0f;
    if (sub == 0) {
        for (int s = 0; s < SPLIT - 1; ++s)
#pragma unroll
            for (int t = 0; t < K2; ++t) {
                unsigned ck = slist[(s * QPB + tq) * K2 + t];
                if (ck < nd[K2-1]) net_insert(nd, ck);
            }

        // nd[0..10] = 11 nearest incl. self. Skip self by index at readout.
        float s1x = 0.f, s1y = 0.f, s1z = 0.f;
        float s2x = 0.f, s2y = 0.f, s2z = 0.f;
#pragma unroll
        for (int t = 0; t < K2; ++t) {
            int idx = (int)(nd[t] & 0x1FFFu);
            if (idx != qi) {
                float4 c = sp[idx];
                s1x += c.x; s1y += c.y; s1z += c.z;
                const float* pp = base2 + 3 * idx;
                s2x += __ldg(pp + 0);
                s2y += __ldg(pp + 1);
                s2z += __ldg(pp + 2);
            }
        }
        float q2x = __ldg(base2 + 3*qi + 0);
        float q2y = __ldg(base2 + 3*qi + 1);
        float q2z = __ldg(base2 + 3*qi + 2);

        const float inv = 1.0f / (float)KNN;
        acc = fabsf((s1x*inv - q.x) - (s2x*inv - q2x))
            + fabsf((s1y*inv - q.y) - (s2y*inv - q2y))
            + fabsf((s1z*inv - q.z) - (s2z*inv - q2z));
    }

    // Deterministic block reduction over 16 warps (non-owner lanes carry 0).
    __syncthreads();
    __shared__ float sred[BLOCK / 32];
#pragma unroll
    for (int o = 16; o > 0; o >>= 1)
        acc += __shfl_down_sync(0xffffffffu, acc, o);
    if ((threadIdx.x & 31) == 0) sred[threadIdx.x >> 5] = acc;
    __syncthreads();
    if (threadIdx.x == 0) {
        float s = 0.f;
#pragma unroll
        for (int w = 0; w < BLOCK / 32; ++w) s += sred[w];
        g_partial[blockIdx.y * BPB + blockIdx.x] = s;
    }
}

__global__ void finalize_kernel(float* __restrict__ out)
{
    __shared__ float s[NBLOCKS];
    int t = threadIdx.x;
    s[t] = g_partial[t];
    __syncthreads();
#pragma unroll
    for (int o = NBLOCKS / 2; o > 0; o >>= 1) {
        if (t < o) s[t] += s[t + o];
        __syncthreads();
    }
    if (t == 0) out[0] = s[0] * (1.0f / (float)(NB * NPTS * 3));
}

extern "C" void kernel_launch(void* const* d_in, const int* in_sizes, int n_in,
                              void* d_out, int out_size)
{
    (void)in_sizes; (void)n_in; (void)out_size;
    const float* p1 = (const float*)d_in[0];
    const float* p2 = (const float*)d_in[1];

    cudaFuncSetAttribute(knn_lap_kernel,
                         cudaFuncAttributeMaxDynamicSharedMemorySize,
                         SMEM_TOTAL);

    dim3 grid(BPB, NB);
    knn_lap_kernel<<<grid, BLOCK, SMEM_TOTAL>>>(p1, p2);
    finalize_kernel<<<1, NBLOCKS>>>((float*)d_out);
}

// round 14
// speedup vs baseline: 1.8620x; 1.0872x over previous
#include <cuda_runtime.h>

#define NPTS   8192
#define NB     2
#define KNN    10
#define K2     11               /* KNN + self slot                    */
#define QPB    128              /* queries per CTA                    */
#define SPLIT  4                /* threads per query                  */
#define BLOCK  (QPB * SPLIT)    /* 512                                */
#define LSUB   (NPTS / SPLIT)   /* 2048 candidates per thread         */
#define BPB    (NPTS / QPB)     /* 64 blocks per batch                */
#define NBLOCKS (NB * BPB)      /* 128 total blocks                   */
#define VEC    16               /* candidates per block               */
#define NPAIR  (VEC / 2)        /* f32x2 pairs per block              */

#define SMEM_SP_BYTES   (NPTS * 16)                       /* 131072 */
#define SMEM_LIST_U32   (QPB * (SPLIT - 1) * K2)          /* 4224   */
#define SMEM_THR_U32    (2 * QPB * SPLIT)                 /* double-buffered */
#define SMEM_TOTAL      (SMEM_SP_BYTES + (SMEM_LIST_U32 + SMEM_THR_U32) * 4)

__device__ float g_partial[NBLOCKS];

__device__ __forceinline__ void net_insert(unsigned nd[K2], unsigned ck)
{
    bool tk[K2];
#pragma unroll
    for (int t = 0; t < K2; ++t) tk[t] = ck < nd[t];
#pragma unroll
    for (int t = K2 - 1; t >= 1; --t)
        nd[t] = tk[t] ? (tk[t-1] ? nd[t-1] : ck) : nd[t];
    nd[0] = tk[0] ? ck : nd[0];
}

__device__ __forceinline__ unsigned min16(const unsigned k[VEC])
{
    unsigned a0 = min(k[0], k[1]),  a1 = min(k[2], k[3]);
    unsigned a2 = min(k[4], k[5]),  a3 = min(k[6], k[7]);
    unsigned a4 = min(k[8], k[9]),  a5 = min(k[10], k[11]);
    unsigned a6 = min(k[12], k[13]), a7 = min(k[14], k[15]);
    unsigned b0 = min(a0, a1), b1 = min(a2, a3);
    unsigned b2 = min(a4, a5), b3 = min(a6, a7);
    return min(min(b0, b1), min(b2, b3));
}

__device__ __forceinline__ unsigned long long pack2(float a)
{
    unsigned long long u = (unsigned long long)__float_as_uint(a);
    return u | (u << 32);
}

// Packed distance for candidate pair p: d2 = w + qw - 2(x qx + y qy + z qz),
// evaluated per 32-bit lane of f32x2 in the SAME op order as the scalar chain
// (bit-identical results; self still computes to exactly 0 before the clamp).
__device__ __forceinline__ void d2_pair(
    const ulonglong2* __restrict__ spp2, int p,
    unsigned long long nx, unsigned long long ny, unsigned long long nz,
    unsigned long long qw2, float& d0, float& d1)
{
    ulonglong2 A = spp2[2*p];      // .x = (x0,x1) .y = (y0,y1)
    ulonglong2 B = spp2[2*p+1];    // .x = (z0,z1) .y = (w0,w1)
    unsigned long long acc;
    asm("{\n\t"
        ".reg .b64 t;\n\t"
        "add.rn.f32x2 t, %1, %2;\n\t"
        "fma.rn.f32x2 t, %3, %4, t;\n\t"
        "fma.rn.f32x2 t, %5, %6, t;\n\t"
        "fma.rn.f32x2 %0, %7, %8, t;\n\t"
        "}"
        : "=l"(acc)
        : "l"(B.y), "l"(qw2), "l"(B.x), "l"(nz),
          "l"(A.y), "l"(ny),  "l"(A.x), "l"(nx));
    uint2 r = *reinterpret_cast<uint2*>(&acc);
    d0 = __uint_as_float(r.x);
    d1 = __uint_as_float(r.y);
}

#define EVAL_BLOCK(key, p0)                                                   \
    do {                                                                      \
        _Pragma("unroll")                                                     \
        for (int _u = 0; _u < NPAIR; ++_u) {                                  \
            float _d0, _d1;                                                   \
            d2_pair(spp2, (p0) + _u, nx, ny, nz, qw2, _d0, _d1);              \
            _d0 = fmaxf(_d0, 0.0f);                                           \
            _d1 = fmaxf(_d1, 0.0f);                                           \
            int _j = ((p0) + _u) * 2;                                         \
            key[2*_u]   = (__float_as_uint(_d0) & 0xFFFFE000u) | (unsigned)_j;     \
            key[2*_u+1] = (__float_as_uint(_d1) & 0xFFFFE000u) | (unsigned)(_j+1); \
        }                                                                     \
    } while (0)

__global__ void __launch_bounds__(BLOCK, 1) knn_lap_kernel(
    const float* __restrict__ p1, const float* __restrict__ p2)
{
    extern __shared__ char smem_raw[];
    float4*     spp   = (float4*)smem_raw;                 // pair layout, 128 KB
    const ulonglong2* spp2 = (const ulonglong2*)smem_raw;
    unsigned*   slist = (unsigned*)(smem_raw + SMEM_SP_BYTES);
    unsigned*   sthr  = slist + SMEM_LIST_U32;             // [2][QPB][SPLIT]

    const int b = blockIdx.y;
    const float* base1 = p1 + (size_t)b * NPTS * 3;
    const float* base2 = p2 + (size_t)b * NPTS * 3;

    // Stage batch-b point1 cloud in PAIR layout:
    //   spp[2p]   = (x0, x1, y0, y1)
    //   spp[2p+1] = (z0, z1, w0, w1)   w = |p|^2 (same formula as before)
    for (int p = threadIdx.x; p < NPTS/2; p += BLOCK) {
        const float* s0 = base1 + 6*p;
        float x0 = s0[0], y0 = s0[1], z0 = s0[2];
        float x1 = s0[3], y1 = s0[4], z1 = s0[5];
        float w0 = fmaf(x0, x0, fmaf(y0, y0, z0*z0));
        float w1 = fmaf(x1, x1, fmaf(y1, y1, z1*z1));
        spp[2*p]   = make_float4(x0, x1, y0, y1);
        spp[2*p+1] = make_float4(z0, z1, w0, w1);
    }
    __syncthreads();

    const int tq  = threadIdx.x & (QPB - 1);   // query slot within CTA
    const int sub = threadIdx.x >> 7;          // substream 0..3
    const int qi  = blockIdx.x * QPB + tq;     // global query index

    // Fetch own query point from pair layout.
    float qx, qy, qz, qw;
    {
        float4 A = spp[(qi >> 1) * 2];
        float4 B = spp[(qi >> 1) * 2 + 1];
        bool hi = qi & 1;
        qx = hi ? A.y : A.x;  qy = hi ? A.w : A.z;
        qz = hi ? B.y : B.x;  qw = hi ? B.w : B.z;
    }
    const unsigned long long nx  = pack2(-2.0f * qx);
    const unsigned long long ny  = pack2(-2.0f * qy);
    const unsigned long long nz  = pack2(-2.0f * qz);
    const unsigned long long qw2 = pack2(qw);

    // K2-smallest packed keys (truncated d2 | 13-bit index); self -> key == qi.
    unsigned nd[K2];
#pragma unroll
    for (int t = 0; t < K2; ++t) nd[t] = 0xFFFFFFFFu;

    int p0 = sub * (LSUB / 2);                 // pair cursor

    // ---- Warm-up: first 2 blocks (32 candidates) inserted UNCONDITIONALLY.
    // No branches, no trip machinery; nd becomes exact top-11 of first 32.
#pragma unroll 1
    for (int blk = 0; blk < 2; ++blk, p0 += NPAIR) {
        unsigned key[VEC];
        EVAL_BLOCK(key, p0);
#pragma unroll
        for (int u = 0; u < VEC; ++u) net_insert(nd, key[u]);
    }
    unsigned thresh = nd[K2-1];
    unsigned eff    = thresh;

    // ---- Main scan: geometric segments with a threshold checkpoint before each.
    const int segs[6] = {2, 4, 8, 16, 32, 64};   // blocks; 2+126 = 128 total
#pragma unroll
    for (int sgi = 0; sgi < 6; ++sgi) {
        // Share 11th-best across the 4 substreams (double-buffered by parity).
        const int par = sgi & 1;
        sthr[(par * QPB + tq) * SPLIT + sub] = thresh;
        __syncthreads();
        const unsigned* v = &sthr[(par * QPB + tq) * SPLIT];
        eff = min(eff, min(min(v[0], v[1]), min(v[2], v[3])));

#pragma unroll 1
        for (int blk = 0; blk < segs[sgi]; ++blk, p0 += NPAIR) {
            unsigned key[VEC];
            EVAL_BLOCK(key, p0);
            unsigned mn = min16(key);

            while (mn < eff) {           // rare once eff is tight
                net_insert(nd, mn);
                thresh = nd[K2-1];
                eff = min(eff, thresh);
#pragma unroll
                for (int u = 0; u < VEC; ++u)    // mask inserted key (unique)
                    key[u] = (key[u] == mn) ? 0xFFFFFFFFu : key[u];
                mn = min16(key);
            }
        }
    }

    // Substreams 1..3 publish lists; substream 0 merges 3*K2 foreign keys.
    if (sub) {
#pragma unroll
        for (int t = 0; t < K2; ++t)
            slist[((sub - 1) * QPB + tq) * K2 + t] = nd[t];
    }
    __syncthreads();

    float acc = 0.0f;
    if (sub == 0) {
        for (int s = 0; s < SPLIT - 1; ++s)
#pragma unroll
            for (int t = 0; t < K2; ++t) {
                unsigned ck = slist[(s * QPB + tq) * K2 + t];
                if (ck < nd[K2-1]) net_insert(nd, ck);
            }

        // nd[0..10] = 11 nearest incl. self. Skip self by index at readout.
        float s1x = 0.f, s1y = 0.f, s1z = 0.f;
        float s2x = 0.f, s2y = 0.f, s2z = 0.f;
#pragma unroll
        for (int t = 0; t < K2; ++t) {
            int idx = (int)(nd[t] & 0x1FFFu);
            if (idx != qi) {
                float4 A = spp[(idx >> 1) * 2];
                float4 B = spp[(idx >> 1) * 2 + 1];
                bool hi = idx & 1;
                s1x += hi ? A.y : A.x;
                s1y += hi ? A.w : A.z;
                s1z += hi ? B.y : B.x;
                const float* pp = base2 + 3 * idx;
                s2x += __ldg(pp + 0);
                s2y += __ldg(pp + 1);
                s2z += __ldg(pp + 2);
            }
        }
        float q2x = __ldg(base2 + 3*qi + 0);
        float q2y = __ldg(base2 + 3*qi + 1);
        float q2z = __ldg(base2 + 3*qi + 2);

        const float inv = 1.0f / (float)KNN;
        acc = fabsf((s1x*inv - qx) - (s2x*inv - q2x))
            + fabsf((s1y*inv - qy) - (s2y*inv - q2y))
            + fabsf((s1z*inv - qz) - (s2z*inv - q2z));
    }

    // Deterministic block reduction over 16 warps (non-owner lanes carry 0).
    __syncthreads();
    __shared__ float sred[BLOCK / 32];
#pragma unroll
    for (int o = 16; o > 0; o >>= 1)
        acc += __shfl_down_sync(0xffffffffu, acc, o);
    if ((threadIdx.x & 31) == 0) sred[threadIdx.x >> 5] = acc;
    __syncthreads();
    if (threadIdx.x == 0) {
        float s = 0.f;
#pragma unroll
        for (int w = 0; w < BLOCK / 32; ++w) s += sred[w];
        g_partial[blockIdx.y * BPB + blockIdx.x] = s;
    }
}

__global__ void finalize_kernel(float* __restrict__ out)
{
    __shared__ float s[NBLOCKS];
    int t = threadIdx.x;
    s[t] = g_partial[t];
    __syncthreads();
#pragma unroll
    for (int o = NBLOCKS / 2; o > 0; o >>= 1) {
        if (t < o) s[t] += s[t + o];
        __syncthreads();
    }
    if (t == 0) out[0] = s[0] * (1.0f / (float)(NB * NPTS * 3));
}

extern "C" void kernel_launch(void* const* d_in, const int* in_sizes, int n_in,
                              void* d_out, int out_size)
{
    (void)in_sizes; (void)n_in; (void)out_size;
    const float* p1 = (const float*)d_in[0];
    const float* p2 = (const float*)d_in[1];

    cudaFuncSetAttribute(knn_lap_kernel,
                         cudaFuncAttributeMaxDynamicSharedMemorySize,
                         SMEM_TOTAL);

    dim3 grid(BPB, NB);
    knn_lap_kernel<<<grid, BLOCK, SMEM_TOTAL>>>(p1, p2);
    finalize_kernel<<<1, NBLOCKS>>>((float*)d_out);
}